// round 8
// baseline (speedup 1.0000x reference)
#include <cuda_runtime.h>
#include <math.h>
#include <stdint.h>

#define SK        131072
#define E_CNT     196608
#define H         128
#define N_TOT     4096
#define M_SUB     4
#define K_SUB     8
#define L_LAYERS  4
#define NUM_G     32

// ---------------- scratch (static device memory; no allocations) ----------------
__device__ float g_h[SK * H];     // node features (64 MB)
__device__ float g_aggr[SK * H];  // message aggregation buffer (64 MB)
__device__ float g_mid[SK * H];   // relu intermediate between the two GEMMs (64 MB)

// ---------------- 3xTF32 helpers ----------------
__device__ __forceinline__ void split_tf32(float z, uint32_t& hi, uint32_t& lo) {
    uint32_t zb = __float_as_uint(z);
    hi = zb & 0xFFFFE000u;
    lo = __float_as_uint(z - __uint_as_float(hi));
}

__device__ __forceinline__ void mma_tf32(float* c,
                                         uint32_t a0, uint32_t a1, uint32_t a2, uint32_t a3,
                                         uint32_t b0, uint32_t b1) {
    asm volatile(
        "mma.sync.aligned.m16n8k8.row.col.f32.tf32.tf32.f32 "
        "{%0,%1,%2,%3}, {%4,%5,%6,%7}, {%8,%9}, {%0,%1,%2,%3};"
        : "+f"(c[0]), "+f"(c[1]), "+f"(c[2]), "+f"(c[3])
        : "r"(a0), "r"(a1), "r"(a2), "r"(a3), "r"(b0), "r"(b1));
}

// ================= small kernels =================
__global__ void zero_aggr_kernel() {
    int i = blockIdx.x * blockDim.x + threadIdx.x;
    ((float4*)g_aggr)[i] = make_float4(0.f, 0.f, 0.f, 0.f);
}

__global__ void embed_kernel(const int* __restrict__ x_tokens,
                             const int* __restrict__ node_ids,
                             const float* __restrict__ atom_emb,
                             const float* __restrict__ role_emb) {
    int t = blockIdx.x * blockDim.x + threadIdx.x;
    int node = t >> 5;
    int lane = t & 31;
    int tok = x_tokens[node];
    float vf = (node_ids[node] >= 0) ? 1.0f : 0.0f;
    int is_root = ((node & (K_SUB - 1)) == 0) ? 1 : 0;
    int c = lane * 4;
    float4 a = *(const float4*)(&atom_emb[tok * H + c]);
    float4 r = *(const float4*)(&role_emb[is_root * H + c]);
    float4 o;
    o.x = (a.x + r.x) * vf; o.y = (a.y + r.y) * vf;
    o.z = (a.z + r.z) * vf; o.w = (a.w + r.w) * vf;
    *(float4*)(&g_h[node * H + c]) = o;
}

__global__ void edge_kernel(const int* __restrict__ src,
                            const int* __restrict__ dst,
                            const int* __restrict__ etok,
                            const float* __restrict__ bond_emb) {
    int t = blockIdx.x * blockDim.x + threadIdx.x;
    int e = t >> 5;
    if (e >= E_CNT) return;
    int lane = t & 31;
    int s = src[e], d = dst[e], bt = etok[e];
    int c = lane * 4;
    float4 hv = *(const float4*)(&g_h[s * H + c]);
    float4 bv = *(const float4*)(&bond_emb[bt * H + c]);
    float4 m;
    m.x = fmaxf(hv.x + bv.x, 0.f); m.y = fmaxf(hv.y + bv.y, 0.f);
    m.z = fmaxf(hv.z + bv.z, 0.f); m.w = fmaxf(hv.w + bv.w, 0.f);
    float* zp = &g_aggr[d * H + c];
    asm volatile("red.global.add.v4.f32 [%0], {%1, %2, %3, %4};"
                 :: "l"(zp), "f"(m.x), "f"(m.y), "f"(m.z), "f"(m.w) : "memory");
}

// ================= 3xTF32 mma.sync GEMM =================
// MODE 1: Z=(1+eps)*h+aggr ; out = relu(Z@W1+b1) -> g_mid     (optionally zero aggr)
// MODE 2: Z=g_mid          ; out = (Z@W2+b2)*vf  -> g_h
//
// Persistent (grid=148, 1 block/SM). 512 threads = 16 warps (4 row x 4 col groups).
// Block tile 64x128, warp tile 16x32. Both A and W live in smem PRE-SPLIT into
// (hi,lo) float2 pairs -> zero split ALU in the K loop, LDS.64 fetches both.
#define TILE_R  64
#define NTILES  (SK / TILE_R)               // 2048
#define ZP      132                          // zs stride in float2
#define WPSTR   132                          // wp stride in float2
#define ZS_FLOATS (TILE_R * ZP * 2)         // 16896 floats
#define SMEMB   (ZS_FLOATS * 4 + H * WPSTR * 8)   // 67584 + 135168 = 202752
#define GRID_G  148

template <int MODE>
__global__ __launch_bounds__(512, 1)
void gemm_kernel(const float* __restrict__ W, const float* __restrict__ bias,
                 const float* __restrict__ eps, int l, int zero_next,
                 const int* __restrict__ node_ids) {
    extern __shared__ float sm[];
    float2* zs = (float2*)sm;                  // [64][132] (hi,lo) pairs
    float2* wp = (float2*)(sm + ZS_FLOATS);    // [128][132] (hi,lo) pairs

    const int tid  = threadIdx.x;
    const int w    = tid >> 5;
    const int lane = tid & 31;
    const int gid  = lane >> 2;        // 0..7
    const int tig  = lane & 3;         // 0..3
    const int wr   = (w & 3) * 16;     // warp row offset (0/16/32/48)
    const int wc   = (w >> 2) * 32;    // warp col offset (0/32/64/96)

    // ---- stage W^T pre-split into (hi,lo) pairs (once per kernel)
#pragma unroll
    for (int i = 0; i < 8; i++) {
        int idx4 = tid + i * 512;
        int k  = idx4 >> 5;
        int n0 = (idx4 & 31) << 2;
        float4 w4 = ((const float4*)W)[idx4];
        float wv[4] = {w4.x, w4.y, w4.z, w4.w};
#pragma unroll
        for (int j = 0; j < 4; j++) {
            uint32_t hb, lb;
            split_tf32(wv[j], hb, lb);
            wp[(n0 + j) * WPSTR + k] =
                make_float2(__uint_as_float(hb), __uint_as_float(lb));
        }
    }

    // ---- bias for this thread's 8 columns, in registers
    float bcol[8];
#pragma unroll
    for (int i = 0; i < 4; i++) {
        float2 b2 = *(const float2*)&bias[wc + 8 * i + 2 * tig];
        bcol[2 * i] = b2.x; bcol[2 * i + 1] = b2.y;
    }
    const float epsl = (MODE == 1) ? (1.0f + eps[l]) : 0.0f;
    __syncthreads();

    for (int t = blockIdx.x; t < NTILES; t += gridDim.x) {
        const int row0 = t * TILE_R;

        // ---- stage Z tile pre-split (coalesced float4 reads; 2048 float4s)
#pragma unroll
        for (int i = 0; i < 4; i++) {
            int idx4 = tid + i * 512;
            int r = idx4 >> 5;
            int c = (idx4 & 31) << 2;
            float4 z4;
            if (MODE == 1) {
                float4 h4 = *(const float4*)&g_h[(row0 + r) * H + c];
                float4 a4 = *(const float4*)&g_aggr[(row0 + r) * H + c];
                z4.x = epsl * h4.x + a4.x; z4.y = epsl * h4.y + a4.y;
                z4.z = epsl * h4.z + a4.z; z4.w = epsl * h4.w + a4.w;
                if (zero_next)
                    *(float4*)&g_aggr[(row0 + r) * H + c] = make_float4(0.f, 0.f, 0.f, 0.f);
            } else {
                z4 = *(const float4*)&g_mid[(row0 + r) * H + c];
            }
            float zv[4] = {z4.x, z4.y, z4.z, z4.w};
            float2* zrow = &zs[r * ZP + c];
#pragma unroll
            for (int j = 0; j < 4; j++) {
                uint32_t hb, lb;
                split_tf32(zv[j], hb, lb);
                zrow[j] = make_float2(__uint_as_float(hb), __uint_as_float(lb));
            }
        }
        __syncthreads();

        // ---- accumulators (4 n-frags x 4), init with bias
        float acc[4][4];
#pragma unroll
        for (int i = 0; i < 4; i++) {
            acc[i][0] = bcol[2 * i];     acc[i][1] = bcol[2 * i + 1];
            acc[i][2] = bcol[2 * i];     acc[i][3] = bcol[2 * i + 1];
        }

        // ---- 3xTF32 K loop: zero split ALU, pure LDS.64 + MMA
        const float2* za = &zs[(wr + gid) * ZP + tig];        // row gid
        const float2* zb = za + 8 * ZP;                       // row gid+8
#pragma unroll 4
        for (int k0 = 0; k0 < H; k0 += 8) {
            float2 pa0 = za[k0];          // (gid,   k0+tig)
            float2 pa1 = zb[k0];          // (gid+8, k0+tig)
            float2 pa2 = za[k0 + 4];      // (gid,   k0+tig+4)
            float2 pa3 = zb[k0 + 4];      // (gid+8, k0+tig+4)
            uint32_t ah0 = __float_as_uint(pa0.x), al0 = __float_as_uint(pa0.y);
            uint32_t ah1 = __float_as_uint(pa1.x), al1 = __float_as_uint(pa1.y);
            uint32_t ah2 = __float_as_uint(pa2.x), al2 = __float_as_uint(pa2.y);
            uint32_t ah3 = __float_as_uint(pa3.x), al3 = __float_as_uint(pa3.y);
#pragma unroll
            for (int i = 0; i < 4; i++) {
                const float2* wq = &wp[(wc + 8 * i + gid) * WPSTR + k0 + tig];
                float2 p0 = wq[0];
                float2 p1 = wq[4];
                uint32_t bh0 = __float_as_uint(p0.x), bl0 = __float_as_uint(p0.y);
                uint32_t bh1 = __float_as_uint(p1.x), bl1 = __float_as_uint(p1.y);
                mma_tf32(acc[i], ah0, ah1, ah2, ah3, bh0, bh1);
                mma_tf32(acc[i], al0, al1, al2, al3, bh0, bh1);
                mma_tf32(acc[i], ah0, ah1, ah2, ah3, bl0, bl1);
            }
        }

        // ---- epilogue straight to global (rows wr+gid, wr+gid+8)
        float* dstb = (MODE == 1) ? g_mid : g_h;
        const int r0g = row0 + wr + gid;
        const int r1g = r0g + 8;
        float vf0 = 1.0f, vf1 = 1.0f;
        if (MODE == 2) {
            vf0 = (node_ids[r0g] >= 0) ? 1.0f : 0.0f;
            vf1 = (node_ids[r1g] >= 0) ? 1.0f : 0.0f;
        }
#pragma unroll
        for (int i = 0; i < 4; i++) {
            int n = wc + 8 * i + 2 * tig;
            float2 v0, v1;
            if (MODE == 1) {
                v0 = make_float2(fmaxf(acc[i][0], 0.f), fmaxf(acc[i][1], 0.f));
                v1 = make_float2(fmaxf(acc[i][2], 0.f), fmaxf(acc[i][3], 0.f));
            } else {
                v0 = make_float2(acc[i][0] * vf0, acc[i][1] * vf0);
                v1 = make_float2(acc[i][2] * vf1, acc[i][3] * vf1);
            }
            *(float2*)&dstb[r0g * H + n] = v0;
            *(float2*)&dstb[r1g * H + n] = v1;
        }
        __syncthreads();   // protect zs before next tile's staging
    }
}

// ================= pooling =================
__global__ void zero_out_kernel(float* __restrict__ out, int n) {
    int i = blockIdx.x * blockDim.x + threadIdx.x;
    if (i < n) out[i] = 0.0f;
}

__global__ void pool_kernel(const int* __restrict__ node_ids,
                            const float* __restrict__ log_probs,
                            const int* __restrict__ batch_graph,
                            const float* __restrict__ ht_alpha,
                            float* __restrict__ out) {
    __shared__ float wgt[M_SUB];
    __shared__ float cinv[M_SUB];
    __shared__ int   nid_s[M_SUB * K_SUB];
    int n = blockIdx.x;
    int tid = threadIdx.x;

    if (tid < M_SUB * K_SUB) nid_s[tid] = node_ids[n * (M_SUB * K_SUB) + tid];
    __syncthreads();

    if (tid < M_SUB) {
        int c = 0;
#pragma unroll
        for (int kk = 0; kk < K_SUB; kk++) c += (nid_s[tid * K_SUB + kk] >= 0);
        cinv[tid] = 1.0f / fmaxf((float)c, 1.0f);
    }
    if (tid == 0) {
        float alpha = ht_alpha[0];
        float v[M_SUB];
        float mx = -3.4e38f;
#pragma unroll
        for (int mm = 0; mm < M_SUB; mm++) {
            float lp = log_probs[n * M_SUB + mm];
            if (!isfinite(lp)) lp = 0.0f;
            v[mm] = -alpha * lp;
            mx = fmaxf(mx, v[mm]);
        }
        float sum = 0.0f;
#pragma unroll
        for (int mm = 0; mm < M_SUB; mm++) { v[mm] = expf(v[mm] - mx); sum += v[mm]; }
#pragma unroll
        for (int mm = 0; mm < M_SUB; mm++) wgt[mm] = v[mm] / sum;
    }
    __syncthreads();

    int d = tid;
    float val = 0.0f;
#pragma unroll
    for (int mm = 0; mm < M_SUB; mm++) {
        float s = 0.0f;
#pragma unroll
        for (int kk = 0; kk < K_SUB; kk++) {
            int fi = n * (M_SUB * K_SUB) + mm * K_SUB + kk;
            if (nid_s[mm * K_SUB + kk] >= 0) s += g_h[fi * H + d];
        }
        val += wgt[mm] * s * cinv[mm];
    }
    atomicAdd(&out[batch_graph[n] * H + d], val);
}

// ================= launch =================
extern "C" void kernel_launch(void* const* d_in, const int* in_sizes, int n_in,
                              void* d_out, int out_size) {
    const int*   x_tokens    = (const int*)d_in[0];
    const int*   edge_tokens = (const int*)d_in[1];
    const int*   intra_ei    = (const int*)d_in[2];
    const int*   node_ids    = (const int*)d_in[3];
    const float* log_probs   = (const float*)d_in[6];
    const int*   batch_graph = (const int*)d_in[7];
    const float* atom_emb    = (const float*)d_in[8];
    const float* bond_emb    = (const float*)d_in[9];
    const float* role_emb    = (const float*)d_in[10];
    const float* eps         = (const float*)d_in[11];
    const float* w1          = (const float*)d_in[12];
    const float* b1          = (const float*)d_in[13];
    const float* w2          = (const float*)d_in[14];
    const float* b2          = (const float*)d_in[15];
    const float* ht_alpha    = (const float*)d_in[16];
    float* out = (float*)d_out;

    const int* src = intra_ei;
    const int* dst = intra_ei + E_CNT;

    (void)cudaFuncSetAttribute(gemm_kernel<1>, cudaFuncAttributeMaxDynamicSharedMemorySize, SMEMB);
    (void)cudaFuncSetAttribute(gemm_kernel<2>, cudaFuncAttributeMaxDynamicSharedMemorySize, SMEMB);

    embed_kernel<<<(SK * 32) / 256, 256>>>(x_tokens, node_ids, atom_emb, role_emb);
    zero_aggr_kernel<<<(SK * H / 4) / 256, 256>>>();

    for (int l = 0; l < L_LAYERS; l++) {
        edge_kernel<<<(E_CNT * 32) / 256, 256>>>(src, dst, edge_tokens, bond_emb);
        gemm_kernel<1><<<GRID_G, 512, SMEMB>>>(
            w1 + l * H * H, b1 + l * H, eps, l, (l < L_LAYERS - 1) ? 1 : 0, node_ids);
        gemm_kernel<2><<<GRID_G, 512, SMEMB>>>(
            w2 + l * H * H, b2 + l * H, (const float*)0, 0, 0, node_ids);
    }

    zero_out_kernel<<<(NUM_G * H + 255) / 256, 256>>>(out, NUM_G * H);
    pool_kernel<<<N_TOT, H>>>(node_ids, log_probs, batch_graph, ht_alpha, out);
}

// round 9
// speedup vs baseline: 1.3559x; 1.3559x over previous
#include <cuda_runtime.h>
#include <math.h>
#include <stdint.h>

#define SK        131072
#define E_CNT     196608
#define H         128
#define N_TOT     4096
#define M_SUB     4
#define K_SUB     8
#define L_LAYERS  4
#define NUM_G     32

// ---------------- scratch (static device memory; no allocations) ----------------
__device__ float g_h[SK * H];     // node features (64 MB)
__device__ float g_aggr[SK * H];  // message aggregation buffer (64 MB)
__device__ float g_mid[SK * H];   // relu intermediate between the two GEMMs (64 MB)

// ---------------- 3xTF32 helpers ----------------
__device__ __forceinline__ void split_tf32(float z, uint32_t& hi, uint32_t& lo) {
    uint32_t zb = __float_as_uint(z);
    hi = zb & 0xFFFFE000u;
    lo = __float_as_uint(z - __uint_as_float(hi));
}

__device__ __forceinline__ void mma_tf32(float* c,
                                         uint32_t a0, uint32_t a1, uint32_t a2, uint32_t a3,
                                         uint32_t b0, uint32_t b1) {
    asm volatile(
        "mma.sync.aligned.m16n8k8.row.col.f32.tf32.tf32.f32 "
        "{%0,%1,%2,%3}, {%4,%5,%6,%7}, {%8,%9}, {%0,%1,%2,%3};"
        : "+f"(c[0]), "+f"(c[1]), "+f"(c[2]), "+f"(c[3])
        : "r"(a0), "r"(a1), "r"(a2), "r"(a3), "r"(b0), "r"(b1));
}

// ================= small kernels =================
__global__ void zero_aggr_kernel() {
    int i = blockIdx.x * blockDim.x + threadIdx.x;
    ((float4*)g_aggr)[i] = make_float4(0.f, 0.f, 0.f, 0.f);
}

__global__ void embed_kernel(const int* __restrict__ x_tokens,
                             const int* __restrict__ node_ids,
                             const float* __restrict__ atom_emb,
                             const float* __restrict__ role_emb) {
    int t = blockIdx.x * blockDim.x + threadIdx.x;
    int node = t >> 5;
    int lane = t & 31;
    int tok = x_tokens[node];
    float vf = (node_ids[node] >= 0) ? 1.0f : 0.0f;
    int is_root = ((node & (K_SUB - 1)) == 0) ? 1 : 0;
    int c = lane * 4;
    float4 a = *(const float4*)(&atom_emb[tok * H + c]);
    float4 r = *(const float4*)(&role_emb[is_root * H + c]);
    float4 o;
    o.x = (a.x + r.x) * vf; o.y = (a.y + r.y) * vf;
    o.z = (a.z + r.z) * vf; o.w = (a.w + r.w) * vf;
    *(float4*)(&g_h[node * H + c]) = o;
}

__global__ void edge_kernel(const int* __restrict__ src,
                            const int* __restrict__ dst,
                            const int* __restrict__ etok,
                            const float* __restrict__ bond_emb) {
    int t = blockIdx.x * blockDim.x + threadIdx.x;
    int e = t >> 5;
    if (e >= E_CNT) return;
    int lane = t & 31;
    int s = src[e], d = dst[e], bt = etok[e];
    int c = lane * 4;
    float4 hv = *(const float4*)(&g_h[s * H + c]);
    float4 bv = *(const float4*)(&bond_emb[bt * H + c]);
    float4 m;
    m.x = fmaxf(hv.x + bv.x, 0.f); m.y = fmaxf(hv.y + bv.y, 0.f);
    m.z = fmaxf(hv.z + bv.z, 0.f); m.w = fmaxf(hv.w + bv.w, 0.f);
    float* zp = &g_aggr[d * H + c];
    asm volatile("red.global.add.v4.f32 [%0], {%1, %2, %3, %4};"
                 :: "l"(zp), "f"(m.x), "f"(m.y), "f"(m.z), "f"(m.w) : "memory");
}

// ================= 3xTF32 mma.sync GEMM (software-pipelined) =================
// MODE 1: Z=(1+eps)*h+aggr ; out = relu(Z@W1+b1) -> g_mid     (optionally zero aggr)
// MODE 2: Z=g_mid          ; out = (Z@W2+b2)*vf  -> g_h
//
// Persistent (grid=148, 1 block/SM). 512 threads = 16 warps (4 row x 4 col groups).
// Block tile 64x128, warp tile 16x32. A and W in smem PRE-SPLIT as (hi,lo) float2.
// 2-stage pipeline: next tile's global loads live in registers during the K loop.
#define TILE_R  64
#define NTILES  (SK / TILE_R)               // 2048
#define ZP      132                          // zs stride in float2
#define WPSTR   132                          // wp stride in float2
#define ZS_FLOATS (TILE_R * ZP * 2)         // 16896 floats
#define SMEMB   (ZS_FLOATS * 4 + H * WPSTR * 8)   // 202752 bytes
#define GRID_G  148

template <int MODE>
__global__ __launch_bounds__(512, 1)
void gemm_kernel(const float* __restrict__ W, const float* __restrict__ bias,
                 const float* __restrict__ eps, int l, int zero_next,
                 const int* __restrict__ node_ids) {
    extern __shared__ float sm[];
    float2* zs = (float2*)sm;                  // [64][132] (hi,lo) pairs
    float2* wp = (float2*)(sm + ZS_FLOATS);    // [128][132] (hi,lo) pairs

    const int tid  = threadIdx.x;
    const int w    = tid >> 5;
    const int lane = tid & 31;
    const int gid  = lane >> 2;        // 0..7
    const int tig  = lane & 3;         // 0..3
    const int wr   = (w & 3) * 16;     // warp row offset (0/16/32/48)
    const int wc   = (w >> 2) * 32;    // warp col offset (0/32/64/96)

    // ---- stage W^T pre-split into (hi,lo) pairs (once per kernel)
#pragma unroll
    for (int i = 0; i < 8; i++) {
        int idx4 = tid + i * 512;
        int k  = idx4 >> 5;
        int n0 = (idx4 & 31) << 2;
        float4 w4 = ((const float4*)W)[idx4];
        float wv[4] = {w4.x, w4.y, w4.z, w4.w};
#pragma unroll
        for (int j = 0; j < 4; j++) {
            uint32_t hb, lb;
            split_tf32(wv[j], hb, lb);
            wp[(n0 + j) * WPSTR + k] =
                make_float2(__uint_as_float(hb), __uint_as_float(lb));
        }
    }

    // ---- bias for this thread's 8 columns, in registers
    float bcol[8];
#pragma unroll
    for (int i = 0; i < 4; i++) {
        float2 b2 = *(const float2*)&bias[wc + 8 * i + 2 * tig];
        bcol[2 * i] = b2.x; bcol[2 * i + 1] = b2.y;
    }
    const float epsl = (MODE == 1) ? (1.0f + eps[l]) : 0.0f;

    // per-thread staging coordinates: 4 float4 slots
    int srow[4], scol[4];
#pragma unroll
    for (int i = 0; i < 4; i++) {
        int idx4 = tid + i * 512;
        srow[i] = idx4 >> 5;
        scol[i] = (idx4 & 31) << 2;
    }
    __syncthreads();

    // ---- pipeline prologue: load first tile into registers
    float4 ph[4], pa[4];
    {
        const int row0 = blockIdx.x * TILE_R;
#pragma unroll
        for (int i = 0; i < 4; i++) {
            if (MODE == 1) {
                ph[i] = *(const float4*)&g_h[(row0 + srow[i]) * H + scol[i]];
                pa[i] = *(const float4*)&g_aggr[(row0 + srow[i]) * H + scol[i]];
            } else {
                ph[i] = *(const float4*)&g_mid[(row0 + srow[i]) * H + scol[i]];
            }
        }
    }

    for (int t = blockIdx.x; t < NTILES; t += gridDim.x) {
        const int row0 = t * TILE_R;

        // ---- phase 1: split registers -> zs (and zero aggr[t] for next layer)
#pragma unroll
        for (int i = 0; i < 4; i++) {
            float zv[4];
            if (MODE == 1) {
                zv[0] = epsl * ph[i].x + pa[i].x;
                zv[1] = epsl * ph[i].y + pa[i].y;
                zv[2] = epsl * ph[i].z + pa[i].z;
                zv[3] = epsl * ph[i].w + pa[i].w;
                if (zero_next)
                    *(float4*)&g_aggr[(row0 + srow[i]) * H + scol[i]] =
                        make_float4(0.f, 0.f, 0.f, 0.f);
            } else {
                zv[0] = ph[i].x; zv[1] = ph[i].y; zv[2] = ph[i].z; zv[3] = ph[i].w;
            }
            float2* zrow = &zs[srow[i] * ZP + scol[i]];
#pragma unroll
            for (int j = 0; j < 4; j++) {
                uint32_t hb, lb;
                split_tf32(zv[j], hb, lb);
                zrow[j] = make_float2(__uint_as_float(hb), __uint_as_float(lb));
            }
        }
        __syncthreads();

        // ---- phase 2a: prefetch next tile (latency covered by K loop)
        {
            int tn = t + gridDim.x;
            int tc = (tn < NTILES) ? tn : t;      // clamp; discarded on last iter
            const int rn0 = tc * TILE_R;
#pragma unroll
            for (int i = 0; i < 4; i++) {
                if (MODE == 1) {
                    ph[i] = *(const float4*)&g_h[(rn0 + srow[i]) * H + scol[i]];
                    pa[i] = *(const float4*)&g_aggr[(rn0 + srow[i]) * H + scol[i]];
                } else {
                    ph[i] = *(const float4*)&g_mid[(rn0 + srow[i]) * H + scol[i]];
                }
            }
        }

        // ---- phase 2b: accumulators + K loop (pure LDS.64 + MMA)
        float acc[4][4];
#pragma unroll
        for (int i = 0; i < 4; i++) {
            acc[i][0] = bcol[2 * i];     acc[i][1] = bcol[2 * i + 1];
            acc[i][2] = bcol[2 * i];     acc[i][3] = bcol[2 * i + 1];
        }

        const float2* za = &zs[(wr + gid) * ZP + tig];        // row gid
        const float2* zb = za + 8 * ZP;                       // row gid+8
#pragma unroll 4
        for (int k0 = 0; k0 < H; k0 += 8) {
            float2 pa0 = za[k0];
            float2 pa1 = zb[k0];
            float2 pa2 = za[k0 + 4];
            float2 pa3 = zb[k0 + 4];
            uint32_t ah0 = __float_as_uint(pa0.x), al0 = __float_as_uint(pa0.y);
            uint32_t ah1 = __float_as_uint(pa1.x), al1 = __float_as_uint(pa1.y);
            uint32_t ah2 = __float_as_uint(pa2.x), al2 = __float_as_uint(pa2.y);
            uint32_t ah3 = __float_as_uint(pa3.x), al3 = __float_as_uint(pa3.y);
#pragma unroll
            for (int i = 0; i < 4; i++) {
                const float2* wq = &wp[(wc + 8 * i + gid) * WPSTR + k0 + tig];
                float2 p0 = wq[0];
                float2 p1 = wq[4];
                uint32_t bh0 = __float_as_uint(p0.x), bl0 = __float_as_uint(p0.y);
                uint32_t bh1 = __float_as_uint(p1.x), bl1 = __float_as_uint(p1.y);
                mma_tf32(acc[i], ah0, ah1, ah2, ah3, bh0, bh1);
                mma_tf32(acc[i], al0, al1, al2, al3, bh0, bh1);
                mma_tf32(acc[i], ah0, ah1, ah2, ah3, bl0, bl1);
            }
        }

        // ---- phase 3: epilogue straight to global (rows wr+gid, wr+gid+8)
        float* dstb = (MODE == 1) ? g_mid : g_h;
        const int r0g = row0 + wr + gid;
        const int r1g = r0g + 8;
        float vf0 = 1.0f, vf1 = 1.0f;
        if (MODE == 2) {
            vf0 = (node_ids[r0g] >= 0) ? 1.0f : 0.0f;
            vf1 = (node_ids[r1g] >= 0) ? 1.0f : 0.0f;
        }
#pragma unroll
        for (int i = 0; i < 4; i++) {
            int n = wc + 8 * i + 2 * tig;
            float2 v0, v1;
            if (MODE == 1) {
                v0 = make_float2(fmaxf(acc[i][0], 0.f), fmaxf(acc[i][1], 0.f));
                v1 = make_float2(fmaxf(acc[i][2], 0.f), fmaxf(acc[i][3], 0.f));
            } else {
                v0 = make_float2(acc[i][0] * vf0, acc[i][1] * vf0);
                v1 = make_float2(acc[i][2] * vf1, acc[i][3] * vf1);
            }
            *(float2*)&dstb[r0g * H + n] = v0;
            *(float2*)&dstb[r1g * H + n] = v1;
        }
        __syncthreads();   // all reads of zs done before next store phase
    }
}

// ================= pooling =================
__global__ void zero_out_kernel(float* __restrict__ out, int n) {
    int i = blockIdx.x * blockDim.x + threadIdx.x;
    if (i < n) out[i] = 0.0f;
}

__global__ void pool_kernel(const int* __restrict__ node_ids,
                            const float* __restrict__ log_probs,
                            const int* __restrict__ batch_graph,
                            const float* __restrict__ ht_alpha,
                            float* __restrict__ out) {
    __shared__ float wgt[M_SUB];
    __shared__ float cinv[M_SUB];
    __shared__ int   nid_s[M_SUB * K_SUB];
    int n = blockIdx.x;
    int tid = threadIdx.x;

    if (tid < M_SUB * K_SUB) nid_s[tid] = node_ids[n * (M_SUB * K_SUB) + tid];
    __syncthreads();

    if (tid < M_SUB) {
        int c = 0;
#pragma unroll
        for (int kk = 0; kk < K_SUB; kk++) c += (nid_s[tid * K_SUB + kk] >= 0);
        cinv[tid] = 1.0f / fmaxf((float)c, 1.0f);
    }
    if (tid == 0) {
        float alpha = ht_alpha[0];
        float v[M_SUB];
        float mx = -3.4e38f;
#pragma unroll
        for (int mm = 0; mm < M_SUB; mm++) {
            float lp = log_probs[n * M_SUB + mm];
            if (!isfinite(lp)) lp = 0.0f;
            v[mm] = -alpha * lp;
            mx = fmaxf(mx, v[mm]);
        }
        float sum = 0.0f;
#pragma unroll
        for (int mm = 0; mm < M_SUB; mm++) { v[mm] = expf(v[mm] - mx); sum += v[mm]; }
#pragma unroll
        for (int mm = 0; mm < M_SUB; mm++) wgt[mm] = v[mm] / sum;
    }
    __syncthreads();

    int d = tid;
    float val = 0.0f;
#pragma unroll
    for (int mm = 0; mm < M_SUB; mm++) {
        float s = 0.0f;
#pragma unroll
        for (int kk = 0; kk < K_SUB; kk++) {
            int fi = n * (M_SUB * K_SUB) + mm * K_SUB + kk;
            if (nid_s[mm * K_SUB + kk] >= 0) s += g_h[fi * H + d];
        }
        val += wgt[mm] * s * cinv[mm];
    }
    atomicAdd(&out[batch_graph[n] * H + d], val);
}

// ================= launch =================
extern "C" void kernel_launch(void* const* d_in, const int* in_sizes, int n_in,
                              void* d_out, int out_size) {
    const int*   x_tokens    = (const int*)d_in[0];
    const int*   edge_tokens = (const int*)d_in[1];
    const int*   intra_ei    = (const int*)d_in[2];
    const int*   node_ids    = (const int*)d_in[3];
    const float* log_probs   = (const float*)d_in[6];
    const int*   batch_graph = (const int*)d_in[7];
    const float* atom_emb    = (const float*)d_in[8];
    const float* bond_emb    = (const float*)d_in[9];
    const float* role_emb    = (const float*)d_in[10];
    const float* eps         = (const float*)d_in[11];
    const float* w1          = (const float*)d_in[12];
    const float* b1          = (const float*)d_in[13];
    const float* w2          = (const float*)d_in[14];
    const float* b2          = (const float*)d_in[15];
    const float* ht_alpha    = (const float*)d_in[16];
    float* out = (float*)d_out;

    const int* src = intra_ei;
    const int* dst = intra_ei + E_CNT;

    (void)cudaFuncSetAttribute(gemm_kernel<1>, cudaFuncAttributeMaxDynamicSharedMemorySize, SMEMB);
    (void)cudaFuncSetAttribute(gemm_kernel<2>, cudaFuncAttributeMaxDynamicSharedMemorySize, SMEMB);

    embed_kernel<<<(SK * 32) / 256, 256>>>(x_tokens, node_ids, atom_emb, role_emb);
    zero_aggr_kernel<<<(SK * H / 4) / 256, 256>>>();

    for (int l = 0; l < L_LAYERS; l++) {
        edge_kernel<<<(E_CNT * 32) / 256, 256>>>(src, dst, edge_tokens, bond_emb);
        gemm_kernel<1><<<GRID_G, 512, SMEMB>>>(
            w1 + l * H * H, b1 + l * H, eps, l, (l < L_LAYERS - 1) ? 1 : 0, node_ids);
        gemm_kernel<2><<<GRID_G, 512, SMEMB>>>(
            w2 + l * H * H, b2 + l * H, (const float*)0, 0, 0, node_ids);
    }

    zero_out_kernel<<<(NUM_G * H + 255) / 256, 256>>>(out, NUM_G * H);
    pool_kernel<<<N_TOT, H>>>(node_ids, log_probs, batch_graph, ht_alpha, out);
}

// round 10
// speedup vs baseline: 1.3809x; 1.0185x over previous
#include <cuda_runtime.h>
#include <math.h>
#include <stdint.h>

#define SK        131072
#define E_CNT     196608
#define H         128
#define N_TOT     4096
#define M_SUB     4
#define K_SUB     8
#define L_LAYERS  4
#define NUM_G     32

// ---------------- scratch (static device memory; no allocations) ----------------
__device__ float g_h[SK * H];     // node features (64 MB)
__device__ float g_aggr[SK * H];  // message aggregation buffer (64 MB)
__device__ float g_mid[SK * H];   // relu intermediate between the two GEMMs (64 MB)

// ---------------- 3xTF32 helpers ----------------
__device__ __forceinline__ void split_tf32(float z, uint32_t& hi, uint32_t& lo) {
    uint32_t zb = __float_as_uint(z);
    hi = zb & 0xFFFFE000u;
    lo = __float_as_uint(z - __uint_as_float(hi));
}

__device__ __forceinline__ void mma_tf32(float* c,
                                         uint32_t a0, uint32_t a1, uint32_t a2, uint32_t a3,
                                         uint32_t b0, uint32_t b1) {
    asm volatile(
        "mma.sync.aligned.m16n8k8.row.col.f32.tf32.tf32.f32 "
        "{%0,%1,%2,%3}, {%4,%5,%6,%7}, {%8,%9}, {%0,%1,%2,%3};"
        : "+f"(c[0]), "+f"(c[1]), "+f"(c[2]), "+f"(c[3])
        : "r"(a0), "r"(a1), "r"(a2), "r"(a3), "r"(b0), "r"(b1));
}

// ================= small kernels =================
__global__ void zero_aggr_kernel() {
    int i = blockIdx.x * blockDim.x + threadIdx.x;
    ((float4*)g_aggr)[i] = make_float4(0.f, 0.f, 0.f, 0.f);
}

__global__ void embed_kernel(const int* __restrict__ x_tokens,
                             const int* __restrict__ node_ids,
                             const float* __restrict__ atom_emb,
                             const float* __restrict__ role_emb) {
    int t = blockIdx.x * blockDim.x + threadIdx.x;
    int node = t >> 5;
    int lane = t & 31;
    int tok = x_tokens[node];
    float vf = (node_ids[node] >= 0) ? 1.0f : 0.0f;
    int is_root = ((node & (K_SUB - 1)) == 0) ? 1 : 0;
    int c = lane * 4;
    float4 a = *(const float4*)(&atom_emb[tok * H + c]);
    float4 r = *(const float4*)(&role_emb[is_root * H + c]);
    float4 o;
    o.x = (a.x + r.x) * vf; o.y = (a.y + r.y) * vf;
    o.z = (a.z + r.z) * vf; o.w = (a.w + r.w) * vf;
    *(float4*)(&g_h[node * H + c]) = o;
}

__global__ void edge_kernel(const int* __restrict__ src,
                            const int* __restrict__ dst,
                            const int* __restrict__ etok,
                            const float* __restrict__ bond_emb) {
    int t = blockIdx.x * blockDim.x + threadIdx.x;
    int e = t >> 5;
    if (e >= E_CNT) return;
    int lane = t & 31;
    int s = src[e], d = dst[e], bt = etok[e];
    int c = lane * 4;
    float4 hv = *(const float4*)(&g_h[s * H + c]);
    float4 bv = *(const float4*)(&bond_emb[bt * H + c]);
    float4 m;
    m.x = fmaxf(hv.x + bv.x, 0.f); m.y = fmaxf(hv.y + bv.y, 0.f);
    m.z = fmaxf(hv.z + bv.z, 0.f); m.w = fmaxf(hv.w + bv.w, 0.f);
    float* zp = &g_aggr[d * H + c];
    asm volatile("red.global.add.v4.f32 [%0], {%1, %2, %3, %4};"
                 :: "l"(zp), "f"(m.x), "f"(m.y), "f"(m.z), "f"(m.w) : "memory");
}

// ================= 3xTF32 mma.sync GEMM (pipelined, fragment-packed W) =========
// MODE 1: Z=(1+eps)*h+aggr ; out = relu(Z@W1+b1) -> g_mid     (optionally zero aggr)
// MODE 2: Z=g_mid          ; out = (Z@W2+b2)*vf  -> g_h
//
// Persistent (grid=148, 1 block/SM). 512 threads = 16 warps (4 row x 4 col groups).
// Block tile 64x128, warp tile 16x32.
// A: zs (hi,lo) float2, stride 132 (conflict-free LDS.64).
// W: wf fragment-packed float4 (hi0,lo0,hi1,lo1) per lane -> conflict-free LDS.128
//    at immediate offsets. K loop fully unrolled (no address ALU).
#define TILE_R  64
#define NTILES  (SK / TILE_R)               // 2048
#define ZP      132                          // zs stride in float2
#define ZS_FLOATS (TILE_R * ZP * 2)         // 16896 floats
#define WF_FLOAT4S (16 * 16 * 32)           // 8192 float4 = 131072 B
#define SMEMB   (ZS_FLOATS * 4 + WF_FLOAT4S * 16)   // 67584 + 131072 = 198656
#define GRID_G  148

template <int MODE>
__global__ __launch_bounds__(512, 1)
void gemm_kernel(const float* __restrict__ W, const float* __restrict__ bias,
                 const float* __restrict__ eps, int l, int zero_next,
                 const int* __restrict__ node_ids) {
    extern __shared__ float sm[];
    float2* zs = (float2*)sm;                  // [64][132] (hi,lo) pairs
    float4* wf = (float4*)(sm + ZS_FLOATS);    // [k0b 16][i 16][lane 32] frag-packed

    const int tid  = threadIdx.x;
    const int w    = tid >> 5;
    const int lane = tid & 31;
    const int gid  = lane >> 2;        // 0..7
    const int tig  = lane & 3;         // 0..3
    const int wr   = (w & 3) * 16;     // warp row offset (0/16/32/48)
    const int wc   = (w >> 2) * 32;    // warp col offset (0/32/64/96)
    const int ib0  = (w >> 2) * 4;     // first n-block (8 cols each) of this warp

    // ---- stage W^T pre-split into fragment-packed layout (once per kernel)
    // element W[k][n] -> wf[(k/8)*16 + n/8][ (n%8)*4 + (k%8)%4 ] half (k%8)/4
#pragma unroll
    for (int i = 0; i < 8; i++) {
        int idx4 = tid + i * 512;
        int k  = idx4 >> 5;
        int n0 = (idx4 & 31) << 2;
        float4 w4 = ((const float4*)W)[idx4];
        float wv[4] = {w4.x, w4.y, w4.z, w4.w};
        int k0b = k >> 3, kk = k & 7, tg = kk & 3, sh = kk >> 2;
#pragma unroll
        for (int j = 0; j < 4; j++) {
            int n = n0 + j;
            uint32_t hb, lb;
            split_tf32(wv[j], hb, lb);
            float2* dstp = (float2*)&wf[(k0b * 16 + (n >> 3)) * 32 + ((n & 7) * 4 + tg)];
            dstp[sh] = make_float2(__uint_as_float(hb), __uint_as_float(lb));
        }
    }

    // ---- bias for this thread's 8 columns, in registers
    float bcol[8];
#pragma unroll
    for (int i = 0; i < 4; i++) {
        float2 b2 = *(const float2*)&bias[wc + 8 * i + 2 * tig];
        bcol[2 * i] = b2.x; bcol[2 * i + 1] = b2.y;
    }
    const float epsl = (MODE == 1) ? (1.0f + eps[l]) : 0.0f;

    // per-thread staging coordinates: 4 float4 slots
    int srow[4], scol[4];
#pragma unroll
    for (int i = 0; i < 4; i++) {
        int idx4 = tid + i * 512;
        srow[i] = idx4 >> 5;
        scol[i] = (idx4 & 31) << 2;
    }
    __syncthreads();

    // ---- pipeline prologue: load first tile into registers
    float4 ph[4], pa[4];
    {
        const int row0 = blockIdx.x * TILE_R;
#pragma unroll
        for (int i = 0; i < 4; i++) {
            if (MODE == 1) {
                ph[i] = *(const float4*)&g_h[(row0 + srow[i]) * H + scol[i]];
                pa[i] = *(const float4*)&g_aggr[(row0 + srow[i]) * H + scol[i]];
            } else {
                ph[i] = *(const float4*)&g_mid[(row0 + srow[i]) * H + scol[i]];
            }
        }
    }

    const float4* wbase = wf + ib0 * 32 + lane;   // immediate-offset base for K loop

    for (int t = blockIdx.x; t < NTILES; t += gridDim.x) {
        const int row0 = t * TILE_R;

        // ---- phase 1: split registers -> zs (packed STS.128), zero aggr[t]
#pragma unroll
        for (int i = 0; i < 4; i++) {
            float zv[4];
            if (MODE == 1) {
                zv[0] = epsl * ph[i].x + pa[i].x;
                zv[1] = epsl * ph[i].y + pa[i].y;
                zv[2] = epsl * ph[i].z + pa[i].z;
                zv[3] = epsl * ph[i].w + pa[i].w;
                if (zero_next)
                    *(float4*)&g_aggr[(row0 + srow[i]) * H + scol[i]] =
                        make_float4(0.f, 0.f, 0.f, 0.f);
            } else {
                zv[0] = ph[i].x; zv[1] = ph[i].y; zv[2] = ph[i].z; zv[3] = ph[i].w;
            }
            uint32_t hb[4], lb[4];
#pragma unroll
            for (int j = 0; j < 4; j++) split_tf32(zv[j], hb[j], lb[j]);
            float4* zrow4 = (float4*)&zs[srow[i] * ZP + scol[i]];
            zrow4[0] = make_float4(__uint_as_float(hb[0]), __uint_as_float(lb[0]),
                                   __uint_as_float(hb[1]), __uint_as_float(lb[1]));
            zrow4[1] = make_float4(__uint_as_float(hb[2]), __uint_as_float(lb[2]),
                                   __uint_as_float(hb[3]), __uint_as_float(lb[3]));
        }
        __syncthreads();

        // ---- phase 2a: prefetch next tile (latency covered by K loop)
        {
            int tn = t + gridDim.x;
            int tc = (tn < NTILES) ? tn : t;      // clamp; discarded on last iter
            const int rn0 = tc * TILE_R;
#pragma unroll
            for (int i = 0; i < 4; i++) {
                if (MODE == 1) {
                    ph[i] = *(const float4*)&g_h[(rn0 + srow[i]) * H + scol[i]];
                    pa[i] = *(const float4*)&g_aggr[(rn0 + srow[i]) * H + scol[i]];
                } else {
                    ph[i] = *(const float4*)&g_mid[(rn0 + srow[i]) * H + scol[i]];
                }
            }
        }

        // ---- phase 2b: accumulators + fully-unrolled K loop
        float acc[4][4];
#pragma unroll
        for (int i = 0; i < 4; i++) {
            acc[i][0] = bcol[2 * i];     acc[i][1] = bcol[2 * i + 1];
            acc[i][2] = bcol[2 * i];     acc[i][3] = bcol[2 * i + 1];
        }

        const float2* za = &zs[(wr + gid) * ZP + tig];        // row gid
        const float2* zb = za + 8 * ZP;                       // row gid+8
#pragma unroll
        for (int k0b = 0; k0b < 16; k0b++) {
            const int k0 = k0b * 8;
            float2 pa0 = za[k0];
            float2 pa1 = zb[k0];
            float2 pa2 = za[k0 + 4];
            float2 pa3 = zb[k0 + 4];
            uint32_t ah0 = __float_as_uint(pa0.x), al0 = __float_as_uint(pa0.y);
            uint32_t ah1 = __float_as_uint(pa1.x), al1 = __float_as_uint(pa1.y);
            uint32_t ah2 = __float_as_uint(pa2.x), al2 = __float_as_uint(pa2.y);
            uint32_t ah3 = __float_as_uint(pa3.x), al3 = __float_as_uint(pa3.y);
#pragma unroll
            for (int i = 0; i < 4; i++) {
                float4 wv = wbase[k0b * 512 + i * 32];   // LDS.128, conflict-free
                uint32_t bh0 = __float_as_uint(wv.x), bl0 = __float_as_uint(wv.y);
                uint32_t bh1 = __float_as_uint(wv.z), bl1 = __float_as_uint(wv.w);
                mma_tf32(acc[i], ah0, ah1, ah2, ah3, bh0, bh1);
                mma_tf32(acc[i], al0, al1, al2, al3, bh0, bh1);
                mma_tf32(acc[i], ah0, ah1, ah2, ah3, bl0, bl1);
            }
        }

        // ---- phase 3: epilogue straight to global (rows wr+gid, wr+gid+8)
        float* dstb = (MODE == 1) ? g_mid : g_h;
        const int r0g = row0 + wr + gid;
        const int r1g = r0g + 8;
        float vf0 = 1.0f, vf1 = 1.0f;
        if (MODE == 2) {
            vf0 = (node_ids[r0g] >= 0) ? 1.0f : 0.0f;
            vf1 = (node_ids[r1g] >= 0) ? 1.0f : 0.0f;
        }
#pragma unroll
        for (int i = 0; i < 4; i++) {
            int n = wc + 8 * i + 2 * tig;
            float2 v0, v1;
            if (MODE == 1) {
                v0 = make_float2(fmaxf(acc[i][0], 0.f), fmaxf(acc[i][1], 0.f));
                v1 = make_float2(fmaxf(acc[i][2], 0.f), fmaxf(acc[i][3], 0.f));
            } else {
                v0 = make_float2(acc[i][0] * vf0, acc[i][1] * vf0);
                v1 = make_float2(acc[i][2] * vf1, acc[i][3] * vf1);
            }
            *(float2*)&dstb[r0g * H + n] = v0;
            *(float2*)&dstb[r1g * H + n] = v1;
        }
        __syncthreads();   // all reads of zs done before next store phase
    }
}

// ================= pooling =================
__global__ void zero_out_kernel(float* __restrict__ out, int n) {
    int i = blockIdx.x * blockDim.x + threadIdx.x;
    if (i < n) out[i] = 0.0f;
}

__global__ void pool_kernel(const int* __restrict__ node_ids,
                            const float* __restrict__ log_probs,
                            const int* __restrict__ batch_graph,
                            const float* __restrict__ ht_alpha,
                            float* __restrict__ out) {
    __shared__ float wgt[M_SUB];
    __shared__ float cinv[M_SUB];
    __shared__ int   nid_s[M_SUB * K_SUB];
    int n = blockIdx.x;
    int tid = threadIdx.x;

    if (tid < M_SUB * K_SUB) nid_s[tid] = node_ids[n * (M_SUB * K_SUB) + tid];
    __syncthreads();

    if (tid < M_SUB) {
        int c = 0;
#pragma unroll
        for (int kk = 0; kk < K_SUB; kk++) c += (nid_s[tid * K_SUB + kk] >= 0);
        cinv[tid] = 1.0f / fmaxf((float)c, 1.0f);
    }
    if (tid == 0) {
        float alpha = ht_alpha[0];
        float v[M_SUB];
        float mx = -3.4e38f;
#pragma unroll
        for (int mm = 0; mm < M_SUB; mm++) {
            float lp = log_probs[n * M_SUB + mm];
            if (!isfinite(lp)) lp = 0.0f;
            v[mm] = -alpha * lp;
            mx = fmaxf(mx, v[mm]);
        }
        float sum = 0.0f;
#pragma unroll
        for (int mm = 0; mm < M_SUB; mm++) { v[mm] = expf(v[mm] - mx); sum += v[mm]; }
#pragma unroll
        for (int mm = 0; mm < M_SUB; mm++) wgt[mm] = v[mm] / sum;
    }
    __syncthreads();

    int d = tid;
    float val = 0.0f;
#pragma unroll
    for (int mm = 0; mm < M_SUB; mm++) {
        float s = 0.0f;
#pragma unroll
        for (int kk = 0; kk < K_SUB; kk++) {
            int fi = n * (M_SUB * K_SUB) + mm * K_SUB + kk;
            if (nid_s[mm * K_SUB + kk] >= 0) s += g_h[fi * H + d];
        }
        val += wgt[mm] * s * cinv[mm];
    }
    atomicAdd(&out[batch_graph[n] * H + d], val);
}

// ================= launch =================
extern "C" void kernel_launch(void* const* d_in, const int* in_sizes, int n_in,
                              void* d_out, int out_size) {
    const int*   x_tokens    = (const int*)d_in[0];
    const int*   edge_tokens = (const int*)d_in[1];
    const int*   intra_ei    = (const int*)d_in[2];
    const int*   node_ids    = (const int*)d_in[3];
    const float* log_probs   = (const float*)d_in[6];
    const int*   batch_graph = (const int*)d_in[7];
    const float* atom_emb    = (const float*)d_in[8];
    const float* bond_emb    = (const float*)d_in[9];
    const float* role_emb    = (const float*)d_in[10];
    const float* eps         = (const float*)d_in[11];
    const float* w1          = (const float*)d_in[12];
    const float* b1          = (const float*)d_in[13];
    const float* w2          = (const float*)d_in[14];
    const float* b2          = (const float*)d_in[15];
    const float* ht_alpha    = (const float*)d_in[16];
    float* out = (float*)d_out;

    const int* src = intra_ei;
    const int* dst = intra_ei + E_CNT;

    (void)cudaFuncSetAttribute(gemm_kernel<1>, cudaFuncAttributeMaxDynamicSharedMemorySize, SMEMB);
    (void)cudaFuncSetAttribute(gemm_kernel<2>, cudaFuncAttributeMaxDynamicSharedMemorySize, SMEMB);

    embed_kernel<<<(SK * 32) / 256, 256>>>(x_tokens, node_ids, atom_emb, role_emb);
    zero_aggr_kernel<<<(SK * H / 4) / 256, 256>>>();

    for (int l = 0; l < L_LAYERS; l++) {
        edge_kernel<<<(E_CNT * 32) / 256, 256>>>(src, dst, edge_tokens, bond_emb);
        gemm_kernel<1><<<GRID_G, 512, SMEMB>>>(
            w1 + l * H * H, b1 + l * H, eps, l, (l < L_LAYERS - 1) ? 1 : 0, node_ids);
        gemm_kernel<2><<<GRID_G, 512, SMEMB>>>(
            w2 + l * H * H, b2 + l * H, (const float*)0, 0, 0, node_ids);
    }

    zero_out_kernel<<<(NUM_G * H + 255) / 256, 256>>>(out, NUM_G * H);
    pool_kernel<<<N_TOT, H>>>(node_ids, log_probs, batch_graph, ht_alpha, out);
}